// round 3
// baseline (speedup 1.0000x reference)
#include <cuda_runtime.h>
#include <cstdint>
#include <cstddef>

// ---------------- problem constants (fixed-shape problem) ----------------
#define Hc   128
#define NUc  200000
#define NMc  80000
#define Ec   2000000
#define ELc  500000
#define FDc  512

#define NMH  (NMc * Hc)   // 10,240,000 floats
#define NUH  ((size_t)NUc * Hc)   // 25,600,000 floats

// ---------------- static scratch (no allocations allowed) ----------------
// layout offsets (in floats) into one big device buffer
#define OFF_MOVIE_X   ((size_t)0)
#define OFF_MOVIE_T   ((size_t)1 * NMH)
#define OFF_MOVIE_H   ((size_t)2 * NMH)
#define OFF_MOVIE_SUM ((size_t)3 * NMH)
#define OFF_MOVIE_TMP ((size_t)4 * NMH)
#define OFF_MOVIE_O   ((size_t)5 * NMH)
#define OFF_USER_SUM  ((size_t)6 * NMH)
#define OFF_USER_H    (OFF_USER_SUM + NUH)
#define OFF_USER_O    (OFF_USER_H + NUH)
#define OFF_INVU      (OFF_USER_O + NUH)
#define OFF_INVM      (OFF_INVU + NUc)
#define OFF_GATEM     (OFF_INVM + NMc)
#define OFF_C1        (OFF_GATEM + NMc)
#define OFF_V1        (OFF_C1 + 128)
#define BUF_TOTAL     (OFF_V1 + 128)

__device__ float g_buf[BUF_TOTAL];
__device__ int   g_deg[NUc + NMc];

// ---------------- degree computation ----------------
__global__ void k_deg(const int* __restrict__ src, const int* __restrict__ dst, int E) {
    int e = blockIdx.x * blockDim.x + threadIdx.x;
    if (e < E) {
        atomicAdd(&g_deg[src[e]], 1);
        atomicAdd(&g_deg[NUc + dst[e]], 1);
    }
}

__global__ void k_finalize_deg(float* __restrict__ invU, float* __restrict__ invM,
                               float* __restrict__ gateM) {
    int i = blockIdx.x * blockDim.x + threadIdx.x;
    if (i < NUc) {
        int d = g_deg[i];
        invU[i] = 1.0f / (float)max(d, 1);
    }
    if (i < NMc) {
        int d = g_deg[NUc + i];
        invM[i] = 1.0f / (float)max(d, 1);
        gateM[i] = d > 0 ? 1.0f : 0.0f;
    }
}

// ---------------- tiny matvecs for the collapsed user_init terms ----------------
// c1[n] = sum_k u0[k] * Wl1_um[k,n]
// v1[n] = bl1_mu[n] + sum_k u0[k] * Wr1_mu[k,n]
__global__ void k_vec(const float* __restrict__ u0, const float* __restrict__ Wl1_um,
                      const float* __restrict__ Wr1_mu, const float* __restrict__ bl1_mu,
                      float* __restrict__ c1, float* __restrict__ v1) {
    int n = threadIdx.x;
    float c = 0.0f, v = 0.0f;
    for (int k = 0; k < Hc; k++) {
        float uk = u0[k];
        c += uk * Wl1_um[k * Hc + n];
        v += uk * Wr1_mu[k * Hc + n];
    }
    c1[n] = c;
    v1[n] = bl1_mu[n] + v;
}

// ---------------- SGEMM: C[M,128] = epilogue(A[M,K] @ W[K,128]) ----------------
// epilogue: C = opt_relu( ascale[row]*acc + bias[n] + gate[row]*gvec[n]
//                         + cscale[row]*Cadd[row,n] )
// (null pointers: ascale/cscale -> 1, bias/gvec/Cadd -> 0)
__global__ __launch_bounds__(256) void k_gemm(
    const float* __restrict__ A, const float* __restrict__ W, float* __restrict__ C,
    int M, int K,
    const float* __restrict__ bias,
    const float* __restrict__ ascale,
    const float* __restrict__ Cadd, const float* __restrict__ cscale,
    const float* __restrict__ gate, const float* __restrict__ gvec,
    int do_relu)
{
    __shared__ float As[16][128];
    __shared__ float Ws[16][128];

    int tid = threadIdx.x;
    int tx = tid & 15;        // 0..15 -> output cols tx*8..tx*8+7
    int ty = tid >> 4;        // 0..15 -> output rows ty*8..ty*8+7
    int brow = blockIdx.x * 128;

    float acc[8][8];
#pragma unroll
    for (int i = 0; i < 8; i++)
#pragma unroll
        for (int j = 0; j < 8; j++) acc[i][j] = 0.0f;

    for (int k0 = 0; k0 < K; k0 += 16) {
#pragma unroll
        for (int it = 0; it < 2; it++) {
            int s = it * 256 + tid;
            // A tile: 128 rows x 16 k, float4 along k
            int m  = s >> 2;
            int k4 = (s & 3) << 2;
            int row = brow + m;
            float4 a = make_float4(0.f, 0.f, 0.f, 0.f);
            if (row < M)
                a = *reinterpret_cast<const float4*>(A + (size_t)row * K + k0 + k4);
            As[k4 + 0][m] = a.x;
            As[k4 + 1][m] = a.y;
            As[k4 + 2][m] = a.z;
            As[k4 + 3][m] = a.w;
            // W tile: 16 k x 128 n, float4 along n
            int kw = s >> 5;
            int n4 = (s & 31) << 2;
            *reinterpret_cast<float4*>(&Ws[kw][n4]) =
                *reinterpret_cast<const float4*>(W + (size_t)(k0 + kw) * Hc + n4);
        }
        __syncthreads();

#pragma unroll
        for (int kk = 0; kk < 16; kk++) {
            float4 a0 = *reinterpret_cast<const float4*>(&As[kk][ty * 8]);
            float4 a1 = *reinterpret_cast<const float4*>(&As[kk][ty * 8 + 4]);
            float4 b0 = *reinterpret_cast<const float4*>(&Ws[kk][tx * 8]);
            float4 b1 = *reinterpret_cast<const float4*>(&Ws[kk][tx * 8 + 4]);
            float av[8] = {a0.x, a0.y, a0.z, a0.w, a1.x, a1.y, a1.z, a1.w};
            float bv[8] = {b0.x, b0.y, b0.z, b0.w, b1.x, b1.y, b1.z, b1.w};
#pragma unroll
            for (int i = 0; i < 8; i++)
#pragma unroll
                for (int j = 0; j < 8; j++)
                    acc[i][j] += av[i] * bv[j];
        }
        __syncthreads();
    }

    // epilogue
#pragma unroll
    for (int i = 0; i < 8; i++) {
        int row = brow + ty * 8 + i;
        if (row >= M) continue;
        float as_ = ascale ? ascale[row] : 1.0f;
        float cs_ = cscale ? cscale[row] : 1.0f;
        float g_  = gate   ? gate[row]   : 0.0f;
#pragma unroll
        for (int jj = 0; jj < 2; jj++) {
            int nb = tx * 8 + jj * 4;
            float4 cadd = make_float4(0.f, 0.f, 0.f, 0.f);
            if (Cadd)
                cadd = *reinterpret_cast<const float4*>(Cadd + (size_t)row * Hc + nb);
            float ca[4] = {cadd.x, cadd.y, cadd.z, cadd.w};
            float4 v;
            float* vp = &v.x;
#pragma unroll
            for (int j = 0; j < 4; j++) {
                int n = nb + j;
                float t = acc[i][jj * 4 + j] * as_;
                if (bias) t += bias[n];
                if (gvec) t += g_ * gvec[n];
                if (Cadd) t += cs_ * ca[j];
                if (do_relu) t = fmaxf(t, 0.0f);
                vp[j] = t;
            }
            *reinterpret_cast<float4*>(C + (size_t)row * Hc + nb) = v;
        }
    }
}

// ---------------- edge aggregation: osum[sidx[e]] += feat[gidx[e]] ----------------
// warp per edge, one float4 per lane (128 floats), vector RED (sm_90+)
__global__ void k_agg(const float4* __restrict__ feat, const int* __restrict__ gidx,
                      const int* __restrict__ sidx, float4* __restrict__ osum, int E) {
    int e = (blockIdx.x * blockDim.x + threadIdx.x) >> 5;
    if (e >= E) return;
    int lane = threadIdx.x & 31;
    int g = __ldg(gidx + e);
    int s = __ldg(sidx + e);
    float4 v = __ldg(feat + (size_t)g * 32 + lane);
    atomicAdd(osum + (size_t)s * 32 + lane, v);
}

// ---------------- user_h = relu(user_sum * invU + v1) ----------------
__global__ void k_userh(const float4* __restrict__ usum, const float* __restrict__ invU,
                        const float* __restrict__ v1, float4* __restrict__ uh) {
    int i = blockIdx.x * blockDim.x + threadIdx.x;  // over NU*32 float4s
    if (i >= NUc * 32) return;
    int u  = i >> 5;
    int n4 = (i & 31) << 2;
    float sc = invU[u];
    float4 a = usum[i];
    float4 r;
    r.x = fmaxf(a.x * sc + v1[n4 + 0], 0.0f);
    r.y = fmaxf(a.y * sc + v1[n4 + 1], 0.0f);
    r.z = fmaxf(a.z * sc + v1[n4 + 2], 0.0f);
    r.w = fmaxf(a.w * sc + v1[n4 + 3], 0.0f);
    uh[i] = r;
}

// ---------------- supervision-edge dot products ----------------
__global__ void k_dot(const float4* __restrict__ uo, const float4* __restrict__ mo,
                      const int* __restrict__ lu, const int* __restrict__ lm,
                      float* __restrict__ out, int EL) {
    int e = (blockIdx.x * blockDim.x + threadIdx.x) >> 5;
    if (e >= EL) return;
    int lane = threadIdx.x & 31;
    float4 a = __ldg(uo + (size_t)__ldg(lu + e) * 32 + lane);
    float4 b = __ldg(mo + (size_t)__ldg(lm + e) * 32 + lane);
    float s = a.x * b.x + a.y * b.y + a.z * b.z + a.w * b.w;
#pragma unroll
    for (int o = 16; o; o >>= 1) s += __shfl_xor_sync(0xffffffffu, s, o);
    if (lane == 0) out[e] = s;
}

// ---------------- launcher ----------------
extern "C" void kernel_launch(void* const* d_in, const int* in_sizes, int n_in,
                              void* d_out, int out_size) {
    // weights are the last 14 inputs (robust to whether n_users scalar is an input)
    int wb = n_in - 14;

    const float* movie_feats = (const float*)d_in[0];
    const float* user_init   = (const float*)d_in[1];
    const int*   edge_src    = (const int*)d_in[2];
    const int*   edge_dst    = (const int*)d_in[3];
    const int*   lbl_user    = (const int*)d_in[4];
    const int*   lbl_movie   = (const int*)d_in[5];

    const float* Wm     = (const float*)d_in[wb + 0];
    const float* bm     = (const float*)d_in[wb + 1];
    const float* Wl1_um = (const float*)d_in[wb + 2];
    const float* bl1_um = (const float*)d_in[wb + 3];
    const float* Wr1_um = (const float*)d_in[wb + 4];
    const float* Wl1_mu = (const float*)d_in[wb + 5];
    const float* bl1_mu = (const float*)d_in[wb + 6];
    const float* Wr1_mu = (const float*)d_in[wb + 7];
    const float* Wl2_um = (const float*)d_in[wb + 8];
    const float* bl2_um = (const float*)d_in[wb + 9];
    const float* Wr2_um = (const float*)d_in[wb + 10];
    const float* Wl2_mu = (const float*)d_in[wb + 11];
    const float* bl2_mu = (const float*)d_in[wb + 12];
    const float* Wr2_mu = (const float*)d_in[wb + 13];

    float* out = (float*)d_out;

    float* buf = nullptr;
    int*   deg = nullptr;
    cudaGetSymbolAddress((void**)&buf, g_buf);
    cudaGetSymbolAddress((void**)&deg, g_deg);

    float* movie_x   = buf + OFF_MOVIE_X;
    float* movie_t   = buf + OFF_MOVIE_T;    // movie_t1, reused as movie_t2
    float* movie_h   = buf + OFF_MOVIE_H;
    float* movie_sum = buf + OFF_MOVIE_SUM;
    float* movie_tmp = buf + OFF_MOVIE_TMP;
    float* movie_o   = buf + OFF_MOVIE_O;
    float* user_sum  = buf + OFF_USER_SUM;
    float* user_h    = buf + OFF_USER_H;
    float* user_o    = buf + OFF_USER_O;
    float* invU      = buf + OFF_INVU;
    float* invM      = buf + OFF_INVM;
    float* gateM     = buf + OFF_GATEM;
    float* c1        = buf + OFF_C1;
    float* v1        = buf + OFF_V1;

    const int gemmM_blocks  = NMc / 128;                  // 625
    const int gemmU_blocks  = (NUc + 127) / 128;          // 1563
    const int agg_blocks    = Ec / 8;                     // 250000 (warp/edge, 256 thr)
    const int dot_blocks    = ELc / 8;                    // 62500

    // zero accumulators and degree counters
    cudaMemsetAsync(deg, 0, sizeof(int) * (NUc + NMc));
    cudaMemsetAsync(user_sum, 0, sizeof(float) * NUH);
    cudaMemsetAsync(movie_sum, 0, sizeof(float) * (size_t)NMH);

    // degrees + reciprocal/gate tables
    k_deg<<<(Ec + 255) / 256, 256>>>(edge_src, edge_dst, Ec);
    k_finalize_deg<<<(NUc + 255) / 256, 256>>>(invU, invM, gateM);

    // collapsed user_init terms
    k_vec<<<1, 128>>>(user_init, Wl1_um, Wr1_mu, bl1_mu, c1, v1);

    // movie_x = movie_feats @ Wm + bm
    k_gemm<<<gemmM_blocks, 256>>>(movie_feats, Wm, movie_x, NMc, FDc,
                                  bm, nullptr, nullptr, nullptr, nullptr, nullptr, 0);

    // movie_t1 = movie_x @ Wl1_mu   (transform-first for conv1 user aggregation)
    k_gemm<<<gemmM_blocks, 256>>>(movie_x, Wl1_mu, movie_t, NMc, Hc,
                                  nullptr, nullptr, nullptr, nullptr, nullptr, nullptr, 0);

    // user_sum = segment_sum over edges of movie_t1[edge_dst] into edge_src
    k_agg<<<agg_blocks, 256>>>((const float4*)movie_t, edge_dst, edge_src,
                               (float4*)user_sum, Ec);

    // user_h = relu(user_sum * invU + v1)
    k_userh<<<(NUc * 32 + 255) / 256, 256>>>((const float4*)user_sum, invU, v1,
                                             (float4*)user_h);

    // movie_h = relu(movie_x @ Wr1_um + bl1_um + gateM * c1)
    k_gemm<<<gemmM_blocks, 256>>>(movie_x, Wr1_um, movie_h, NMc, Hc,
                                  bl1_um, nullptr, nullptr, nullptr, gateM, c1, 1);

    // movie_sum = segment_sum of user_h[edge_src] into edge_dst
    k_agg<<<agg_blocks, 256>>>((const float4*)user_h, edge_src, edge_dst,
                               (float4*)movie_sum, Ec);

    // movie_tmp = movie_h @ Wr2_um
    k_gemm<<<gemmM_blocks, 256>>>(movie_h, Wr2_um, movie_tmp, NMc, Hc,
                                  nullptr, nullptr, nullptr, nullptr, nullptr, nullptr, 0);

    // movie_o = invM*(movie_sum @ Wl2_um) + bl2_um + movie_tmp
    k_gemm<<<gemmM_blocks, 256>>>(movie_sum, Wl2_um, movie_o, NMc, Hc,
                                  bl2_um, invM, movie_tmp, nullptr, nullptr, nullptr, 0);

    // movie_t2 = movie_h @ Wl2_mu   (transform-first for conv2 user aggregation)
    k_gemm<<<gemmM_blocks, 256>>>(movie_h, Wl2_mu, movie_t, NMc, Hc,
                                  nullptr, nullptr, nullptr, nullptr, nullptr, nullptr, 0);

    // re-zero user accumulator, then user_sum = segsum of movie_t2[edge_dst] into edge_src
    cudaMemsetAsync(user_sum, 0, sizeof(float) * NUH);
    k_agg<<<agg_blocks, 256>>>((const float4*)movie_t, edge_dst, edge_src,
                               (float4*)user_sum, Ec);

    // user_o = user_h @ Wr2_mu + bl2_mu + invU * user_sum
    k_gemm<<<gemmU_blocks, 256>>>(user_h, Wr2_mu, user_o, NUc, Hc,
                                  bl2_mu, nullptr, user_sum, invU, nullptr, nullptr, 0);

    // out[e] = dot(user_o[lbl_user[e]], movie_o[lbl_movie[e]])
    k_dot<<<dot_blocks, 256>>>((const float4*)user_o, (const float4*)movie_o,
                               lbl_user, lbl_movie, out, ELc);
}

// round 4
// speedup vs baseline: 1.4534x; 1.4534x over previous
#include <cuda_runtime.h>
#include <cstdint>
#include <cstddef>

// ---------------- problem constants (fixed-shape problem) ----------------
#define Hc   128
#define NUc  200000
#define NMc  80000
#define Ec   2000000
#define ELc  500000
#define FDc  512

#define NMH  (NMc * Hc)            // 10,240,000 floats
#define NUH  ((size_t)NUc * Hc)    // 25,600,000 floats

// ---------------- static scratch (no allocations allowed) ----------------
#define OFF_MOVIE_X   ((size_t)0)
#define OFF_T1T2      (OFF_MOVIE_X + NMH)            // interleaved [NM][256]: t1 | t2
#define OFF_MOVIE_H   (OFF_T1T2 + (size_t)2 * NMH)
#define OFF_MOVIE_TMP (OFF_MOVIE_H + NMH)
#define OFF_MSUM      (OFF_MOVIE_TMP + NMH)
#define OFF_MOVIE_O   (OFF_MSUM + NMH)
#define OFF_USER_H    (OFF_MOVIE_O + NMH)
#define OFF_UMEAN2    (OFF_USER_H + NUH)
#define OFF_USER_O    (OFF_UMEAN2 + NUH)
#define OFF_INVM      (OFF_USER_O + NUH)
#define OFF_GATEM     (OFF_INVM + NMc)
#define OFF_C1        (OFF_GATEM + NMc)
#define OFF_V1        (OFF_C1 + 128)
#define BUF_TOTAL     (OFF_V1 + 128)

__device__ float g_buf[BUF_TOTAL];
__device__ int   g_deg[NUc + NMc];

// int scratch: CSR structures
#define IOFF_CSRU   ((size_t)0)                 // E
#define IOFF_CSRM   (IOFF_CSRU + Ec)            // E
#define IOFF_STARTU (IOFF_CSRM + Ec)            // NU+1
#define IOFF_STARTM (IOFF_STARTU + NUc + 1)     // NM+1
#define IOFF_CURSU  (IOFF_STARTM + NMc + 1)     // NU
#define IOFF_CURSM  (IOFF_CURSU + NUc)          // NM
#define IOFF_INCL   (IOFF_CURSM + NMc)          // max(NU,NM)
#define IOFF_BSUM   (IOFF_INCL + NUc)           // 256
#define IBUF_TOTAL  (IOFF_BSUM + 256)

__device__ int g_ibuf[IBUF_TOTAL];

// ---------------- degree counting ----------------
__global__ void k_deg(const int* __restrict__ src, const int* __restrict__ dst, int E) {
    int e = blockIdx.x * blockDim.x + threadIdx.x;
    if (e < E) {
        atomicAdd(&g_deg[src[e]], 1);
        atomicAdd(&g_deg[NUc + dst[e]], 1);
    }
}

// ---------------- scan: phase 1 (per-block inclusive scan + block sums) ----------------
__global__ __launch_bounds__(1024) void k_scan1(const int* __restrict__ deg,
                                                int* __restrict__ incl,
                                                int* __restrict__ bsum, int N) {
    __shared__ int sm[1024];
    int t = threadIdx.x;
    int i = blockIdx.x * 1024 + t;
    int v = (i < N) ? deg[i] : 0;
    sm[t] = v;
    __syncthreads();
#pragma unroll
    for (int o = 1; o < 1024; o <<= 1) {
        int x = (t >= o) ? sm[t - o] : 0;
        __syncthreads();
        sm[t] += x;
        __syncthreads();
    }
    if (i < N) incl[i] = sm[t];
    if (t == 1023) bsum[blockIdx.x] = sm[1023];
}

// ---------------- scan: phase 2 (exclusive scan of block sums, 1 block) ----------------
__global__ void k_scan2(int* __restrict__ bsum, int nb) {
    __shared__ int sm[256];
    int t = threadIdx.x;
    int v = (t < nb) ? bsum[t] : 0;
    sm[t] = v;
    __syncthreads();
#pragma unroll
    for (int o = 1; o < 256; o <<= 1) {
        int x = (t >= o) ? sm[t - o] : 0;
        __syncthreads();
        sm[t] += x;
        __syncthreads();
    }
    if (t < nb) bsum[t] = sm[t] - v;   // exclusive
}

// ---------------- scan: phase 3 (final offsets + cursors + inv/gate tables) ----------------
__global__ void k_scan3(const int* __restrict__ deg, const int* __restrict__ incl,
                        const int* __restrict__ bsum,
                        int* __restrict__ start, int* __restrict__ curs,
                        float* __restrict__ inv, float* __restrict__ gate, int N) {
    int i = blockIdx.x * blockDim.x + threadIdx.x;
    if (i >= N) return;
    int d = deg[i];
    int s = incl[i] - d + bsum[i >> 10];
    start[i] = s;
    curs[i]  = s;
    if (i == N - 1) start[N] = s + d;
    if (inv)  inv[i]  = 1.0f / (float)max(d, 1);
    if (gate) gate[i] = d > 0 ? 1.0f : 0.0f;
}

// ---------------- edge scatter into both CSRs ----------------
__global__ void k_scatter(const int* __restrict__ src, const int* __restrict__ dst,
                          int* __restrict__ cursU, int* __restrict__ cursM,
                          int* __restrict__ csrU, int* __restrict__ csrM, int E) {
    int e = blockIdx.x * blockDim.x + threadIdx.x;
    if (e >= E) return;
    int u = src[e], m = dst[e];
    csrU[atomicAdd(cursU + u, 1)] = m;
    csrM[atomicAdd(cursM + m, 1)] = u;
}

// ---------------- collapsed user_init terms ----------------
__global__ void k_vec(const float* __restrict__ u0, const float* __restrict__ Wl1_um,
                      const float* __restrict__ Wr1_mu, const float* __restrict__ bl1_mu,
                      float* __restrict__ c1, float* __restrict__ v1) {
    int n = threadIdx.x;
    float c = 0.0f, v = 0.0f;
    for (int k = 0; k < Hc; k++) {
        float uk = u0[k];
        c += uk * Wl1_um[k * Hc + n];
        v += uk * Wr1_mu[k * Hc + n];
    }
    c1[n] = c;
    v1[n] = bl1_mu[n] + v;
}

// ---------------- pipelined SGEMM: C[M,128] = epilogue(A[M,K] @ W[K,128]) ----------------
// epilogue: t = ascale[row]*acc + bias[n] + gate[row]*gvec[n] + Cadd[row,n]
//           (null -> scale 1 / term 0); optional relu; output row stride ldc.
__global__ __launch_bounds__(256, 2) void k_gemm(
    const float* __restrict__ A, const float* __restrict__ W, float* __restrict__ C,
    int M, int K, int ldc,
    const float* __restrict__ bias,
    const float* __restrict__ ascale,
    const float* __restrict__ Cadd,
    const float* __restrict__ gate, const float* __restrict__ gvec,
    int do_relu)
{
    __shared__ float As[16][128];
    __shared__ float Ws[16][128];

    int tid = threadIdx.x;
    int tx = tid & 15;         // output cols tx*8 .. tx*8+7
    int ty = tid >> 4;         // output rows ty*8 .. ty*8+7
    int brow = blockIdx.x * 128;

    float acc[8][8];
#pragma unroll
    for (int i = 0; i < 8; i++)
#pragma unroll
        for (int j = 0; j < 8; j++) acc[i][j] = 0.0f;

    float4 a_st[2], w_st[2];

    auto load_tiles = [&](int k0) {
#pragma unroll
        for (int it = 0; it < 2; it++) {
            int s = it * 256 + tid;
            int m = s >> 2;
            int k4 = (s & 3) << 2;
            int row = brow + m;
            a_st[it] = (row < M)
                ? *reinterpret_cast<const float4*>(A + (size_t)row * K + k0 + k4)
                : make_float4(0.f, 0.f, 0.f, 0.f);
            int kw = s >> 5;
            int n4 = (s & 31) << 2;
            w_st[it] = *reinterpret_cast<const float4*>(W + (size_t)(k0 + kw) * Hc + n4);
        }
    };

    load_tiles(0);
    int nt = K >> 4;
    for (int t = 0; t < nt; t++) {
        // stage -> smem
#pragma unroll
        for (int it = 0; it < 2; it++) {
            int s = it * 256 + tid;
            int m = s >> 2;
            int k4 = (s & 3) << 2;
            As[k4 + 0][m] = a_st[it].x;
            As[k4 + 1][m] = a_st[it].y;
            As[k4 + 2][m] = a_st[it].z;
            As[k4 + 3][m] = a_st[it].w;
            int kw = s >> 5;
            int n4 = (s & 31) << 2;
            *reinterpret_cast<float4*>(&Ws[kw][n4]) = w_st[it];
        }
        __syncthreads();

        // prefetch next tile into registers (overlaps with FMAs below)
        if (t + 1 < nt) load_tiles((t + 1) << 4);

#pragma unroll
        for (int kk = 0; kk < 16; kk++) {
            float4 a0 = *reinterpret_cast<const float4*>(&As[kk][ty * 8]);
            float4 a1 = *reinterpret_cast<const float4*>(&As[kk][ty * 8 + 4]);
            float4 b0 = *reinterpret_cast<const float4*>(&Ws[kk][tx * 8]);
            float4 b1 = *reinterpret_cast<const float4*>(&Ws[kk][tx * 8 + 4]);
            float av[8] = {a0.x, a0.y, a0.z, a0.w, a1.x, a1.y, a1.z, a1.w};
            float bv[8] = {b0.x, b0.y, b0.z, b0.w, b1.x, b1.y, b1.z, b1.w};
#pragma unroll
            for (int i = 0; i < 8; i++)
#pragma unroll
                for (int j = 0; j < 8; j++)
                    acc[i][j] += av[i] * bv[j];
        }
        __syncthreads();
    }

    // epilogue
#pragma unroll
    for (int i = 0; i < 8; i++) {
        int row = brow + ty * 8 + i;
        if (row >= M) continue;
        float as_ = ascale ? ascale[row] : 1.0f;
        float g_  = gate   ? gate[row]   : 0.0f;
#pragma unroll
        for (int jj = 0; jj < 2; jj++) {
            int nb = tx * 8 + jj * 4;
            float4 cadd = make_float4(0.f, 0.f, 0.f, 0.f);
            if (Cadd)
                cadd = *reinterpret_cast<const float4*>(Cadd + (size_t)row * Hc + nb);
            float ca[4] = {cadd.x, cadd.y, cadd.z, cadd.w};
            float4 v;
            float* vp = &v.x;
#pragma unroll
            for (int j = 0; j < 4; j++) {
                int n = nb + j;
                float tacc = acc[i][jj * 4 + j] * as_;
                if (bias) tacc += bias[n];
                if (gvec) tacc += g_ * gvec[n];
                if (Cadd) tacc += ca[j];
                if (do_relu) tacc = fmaxf(tacc, 0.0f);
                vp[j] = tacc;
            }
            *reinterpret_cast<float4*>(C + (size_t)row * ldc + nb) = v;
        }
    }
}

// ---------------- fused user aggregation over CSR (t1+t2 interleaved table) ----------------
// uh[u]     = relu( inv * sum_m t1[m] + v1 ),  inv = 1/max(deg,1)
// umean2[u] = inv * sum_m t2[m]
__global__ void k_agg_user(const float4* __restrict__ t1t2, const int* __restrict__ csr,
                           const int* __restrict__ start, const float* __restrict__ v1,
                           float4* __restrict__ uh, float4* __restrict__ umean2) {
    int u = blockIdx.x * (blockDim.x >> 5) + (threadIdx.x >> 5);
    if (u >= NUc) return;
    int lane = threadIdx.x & 31;
    int s = start[u], e = start[u + 1];

    float4 a1 = make_float4(0.f, 0.f, 0.f, 0.f);
    float4 a2 = make_float4(0.f, 0.f, 0.f, 0.f);
    int j = s;
    for (; j + 1 < e; j += 2) {
        int m0 = __ldg(csr + j);
        int m1 = __ldg(csr + j + 1);
        const float4* r0 = t1t2 + (size_t)m0 * 64;
        const float4* r1 = t1t2 + (size_t)m1 * 64;
        float4 x0 = __ldg(r0 + lane);
        float4 y0 = __ldg(r0 + 32 + lane);
        float4 x1 = __ldg(r1 + lane);
        float4 y1 = __ldg(r1 + 32 + lane);
        a1.x += x0.x + x1.x; a1.y += x0.y + x1.y; a1.z += x0.z + x1.z; a1.w += x0.w + x1.w;
        a2.x += y0.x + y1.x; a2.y += y0.y + y1.y; a2.z += y0.z + y1.z; a2.w += y0.w + y1.w;
    }
    if (j < e) {
        int m0 = __ldg(csr + j);
        const float4* r0 = t1t2 + (size_t)m0 * 64;
        float4 x0 = __ldg(r0 + lane);
        float4 y0 = __ldg(r0 + 32 + lane);
        a1.x += x0.x; a1.y += x0.y; a1.z += x0.z; a1.w += x0.w;
        a2.x += y0.x; a2.y += y0.y; a2.z += y0.z; a2.w += y0.w;
    }

    float inv = 1.0f / (float)max(e - s, 1);
    float4 vv = reinterpret_cast<const float4*>(v1)[lane];
    float4 r;
    r.x = fmaxf(a1.x * inv + vv.x, 0.0f);
    r.y = fmaxf(a1.y * inv + vv.y, 0.0f);
    r.z = fmaxf(a1.z * inv + vv.z, 0.0f);
    r.w = fmaxf(a1.w * inv + vv.w, 0.0f);
    float4 m2;
    m2.x = a2.x * inv; m2.y = a2.y * inv; m2.z = a2.z * inv; m2.w = a2.w * inv;
    size_t o = (size_t)u * 32 + lane;
    uh[o] = r;
    umean2[o] = m2;
}

// ---------------- movie aggregation over CSR: msum[m] = sum_u user_h[u] ----------------
__global__ void k_agg_movie(const float4* __restrict__ uh, const int* __restrict__ csr,
                            const int* __restrict__ start, float4* __restrict__ msum) {
    int m = blockIdx.x * (blockDim.x >> 5) + (threadIdx.x >> 5);
    if (m >= NMc) return;
    int lane = threadIdx.x & 31;
    int s = start[m], e = start[m + 1];

    float4 a = make_float4(0.f, 0.f, 0.f, 0.f);
    int j = s;
    for (; j + 1 < e; j += 2) {
        int u0 = __ldg(csr + j);
        int u1 = __ldg(csr + j + 1);
        float4 x0 = __ldg(uh + (size_t)u0 * 32 + lane);
        float4 x1 = __ldg(uh + (size_t)u1 * 32 + lane);
        a.x += x0.x + x1.x; a.y += x0.y + x1.y; a.z += x0.z + x1.z; a.w += x0.w + x1.w;
    }
    if (j < e) {
        float4 x0 = __ldg(uh + (size_t)__ldg(csr + j) * 32 + lane);
        a.x += x0.x; a.y += x0.y; a.z += x0.z; a.w += x0.w;
    }
    msum[(size_t)m * 32 + lane] = a;
}

// ---------------- supervision-edge dot products ----------------
__global__ void k_dot(const float4* __restrict__ uo, const float4* __restrict__ mo,
                      const int* __restrict__ lu, const int* __restrict__ lm,
                      float* __restrict__ out, int EL) {
    int e = (blockIdx.x * blockDim.x + threadIdx.x) >> 5;
    if (e >= EL) return;
    int lane = threadIdx.x & 31;
    float4 a = __ldg(uo + (size_t)__ldg(lu + e) * 32 + lane);
    float4 b = __ldg(mo + (size_t)__ldg(lm + e) * 32 + lane);
    float s = a.x * b.x + a.y * b.y + a.z * b.z + a.w * b.w;
#pragma unroll
    for (int o = 16; o; o >>= 1) s += __shfl_xor_sync(0xffffffffu, s, o);
    if (lane == 0) out[e] = s;
}

// ---------------- launcher ----------------
extern "C" void kernel_launch(void* const* d_in, const int* in_sizes, int n_in,
                              void* d_out, int out_size) {
    int wb = n_in - 14;  // weights are the last 14 inputs

    const float* movie_feats = (const float*)d_in[0];
    const float* user_init   = (const float*)d_in[1];
    const int*   edge_src    = (const int*)d_in[2];
    const int*   edge_dst    = (const int*)d_in[3];
    const int*   lbl_user    = (const int*)d_in[4];
    const int*   lbl_movie   = (const int*)d_in[5];

    const float* Wm     = (const float*)d_in[wb + 0];
    const float* bm     = (const float*)d_in[wb + 1];
    const float* Wl1_um = (const float*)d_in[wb + 2];
    const float* bl1_um = (const float*)d_in[wb + 3];
    const float* Wr1_um = (const float*)d_in[wb + 4];
    const float* Wl1_mu = (const float*)d_in[wb + 5];
    const float* bl1_mu = (const float*)d_in[wb + 6];
    const float* Wr1_mu = (const float*)d_in[wb + 7];
    const float* Wl2_um = (const float*)d_in[wb + 8];
    const float* bl2_um = (const float*)d_in[wb + 9];
    const float* Wr2_um = (const float*)d_in[wb + 10];
    const float* Wl2_mu = (const float*)d_in[wb + 11];
    const float* bl2_mu = (const float*)d_in[wb + 12];
    const float* Wr2_mu = (const float*)d_in[wb + 13];

    float* out = (float*)d_out;

    float* buf = nullptr;
    int*   deg = nullptr;
    int*   ibuf = nullptr;
    cudaGetSymbolAddress((void**)&buf, g_buf);
    cudaGetSymbolAddress((void**)&deg, g_deg);
    cudaGetSymbolAddress((void**)&ibuf, g_ibuf);

    float* movie_x   = buf + OFF_MOVIE_X;
    float* t1t2      = buf + OFF_T1T2;
    float* movie_h   = buf + OFF_MOVIE_H;
    float* movie_tmp = buf + OFF_MOVIE_TMP;
    float* msum      = buf + OFF_MSUM;
    float* movie_o   = buf + OFF_MOVIE_O;
    float* user_h    = buf + OFF_USER_H;
    float* umean2    = buf + OFF_UMEAN2;
    float* user_o    = buf + OFF_USER_O;
    float* invM      = buf + OFF_INVM;
    float* gateM     = buf + OFF_GATEM;
    float* c1        = buf + OFF_C1;
    float* v1        = buf + OFF_V1;

    int* csrU   = ibuf + IOFF_CSRU;
    int* csrM   = ibuf + IOFF_CSRM;
    int* startU = ibuf + IOFF_STARTU;
    int* startM = ibuf + IOFF_STARTM;
    int* cursU  = ibuf + IOFF_CURSU;
    int* cursM  = ibuf + IOFF_CURSM;
    int* incl   = ibuf + IOFF_INCL;
    int* bsum   = ibuf + IOFF_BSUM;

    const int nbU = (NUc + 1023) / 1024;   // 196
    const int nbM = (NMc + 1023) / 1024;   // 79
    const int gemmM_blocks = NMc / 128;                 // 625
    const int gemmU_blocks = (NUc + 127) / 128;         // 1563

    // -------- CSR build --------
    cudaMemsetAsync(deg, 0, sizeof(int) * (NUc + NMc));
    k_deg<<<(Ec + 255) / 256, 256>>>(edge_src, edge_dst, Ec);

    k_scan1<<<nbU, 1024>>>(deg, incl, bsum, NUc);
    k_scan2<<<1, 256>>>(bsum, nbU);
    k_scan3<<<nbU, 1024>>>(deg, incl, bsum, startU, cursU, nullptr, nullptr, NUc);

    k_scan1<<<nbM, 1024>>>(deg + NUc, incl, bsum, NMc);
    k_scan2<<<1, 256>>>(bsum, nbM);
    k_scan3<<<nbM, 1024>>>(deg + NUc, incl, bsum, startM, cursM, invM, gateM, NMc);

    k_scatter<<<(Ec + 255) / 256, 256>>>(edge_src, edge_dst, cursU, cursM, csrU, csrM, Ec);

    // collapsed user_init terms
    k_vec<<<1, 128>>>(user_init, Wl1_um, Wr1_mu, bl1_mu, c1, v1);

    // -------- GEMM chain (movie side) --------
    k_gemm<<<gemmM_blocks, 256>>>(movie_feats, Wm, movie_x, NMc, FDc, Hc,
                                  bm, nullptr, nullptr, nullptr, nullptr, 0);
    k_gemm<<<gemmM_blocks, 256>>>(movie_x, Wl1_mu, t1t2, NMc, Hc, 256,
                                  nullptr, nullptr, nullptr, nullptr, nullptr, 0);
    k_gemm<<<gemmM_blocks, 256>>>(movie_x, Wr1_um, movie_h, NMc, Hc, Hc,
                                  bl1_um, nullptr, nullptr, gateM, c1, 1);
    k_gemm<<<gemmM_blocks, 256>>>(movie_h, Wl2_mu, t1t2 + 128, NMc, Hc, 256,
                                  nullptr, nullptr, nullptr, nullptr, nullptr, 0);
    k_gemm<<<gemmM_blocks, 256>>>(movie_h, Wr2_um, movie_tmp, NMc, Hc, Hc,
                                  nullptr, nullptr, nullptr, nullptr, nullptr, 0);

    // -------- aggregations (CSR gather, no atomics, no memsets) --------
    k_agg_user<<<(NUc + 7) / 8, 256>>>((const float4*)t1t2, csrU, startU, v1,
                                       (float4*)user_h, (float4*)umean2);
    k_agg_movie<<<(NMc + 7) / 8, 256>>>((const float4*)user_h, csrM, startM,
                                        (float4*)msum);

    // -------- output GEMMs --------
    // movie_o = invM*(msum @ Wl2_um) + bl2_um + movie_tmp
    k_gemm<<<gemmM_blocks, 256>>>(msum, Wl2_um, movie_o, NMc, Hc, Hc,
                                  bl2_um, invM, movie_tmp, nullptr, nullptr, 0);
    // user_o = user_h @ Wr2_mu + bl2_mu + umean2
    k_gemm<<<gemmU_blocks, 256>>>(user_h, Wr2_mu, user_o, NUc, Hc, Hc,
                                  bl2_mu, nullptr, umean2, nullptr, nullptr, 0);

    // out[e] = dot(user_o[lbl_user[e]], movie_o[lbl_movie[e]])
    k_dot<<<(ELc + 7) / 8, 256>>>((const float4*)user_o, (const float4*)movie_o,
                                  lbl_user, lbl_movie, out, ELc);
}

// round 6
// speedup vs baseline: 1.5078x; 1.0374x over previous
#include <cuda_runtime.h>
#include <cstdint>
#include <cstddef>

// ---------------- problem constants (fixed-shape problem) ----------------
#define Hc   128
#define NUc  200000
#define NMc  80000
#define Ec   2000000
#define ELc  500000
#define FDc  512

#define NMH  (NMc * Hc)            // 10,240,000 floats
#define NUH  ((size_t)NUc * Hc)    // 25,600,000 floats

// ---------------- static scratch (no allocations allowed) ----------------
#define OFF_MOVIE_X   ((size_t)0)
#define OFF_T1T2      (OFF_MOVIE_X + NMH)            // interleaved [NM][256]: t1 | t2
#define OFF_MOVIE_H   (OFF_T1T2 + (size_t)2 * NMH)
#define OFF_MOVIE_TMP (OFF_MOVIE_H + NMH)
#define OFF_MSUM      (OFF_MOVIE_TMP + NMH)
#define OFF_MOVIE_O   (OFF_MSUM + NMH)
#define OFF_USER_H    (OFF_MOVIE_O + NMH)
#define OFF_UMEAN2    (OFF_USER_H + NUH)
#define OFF_USER_O    (OFF_UMEAN2 + NUH)
#define OFF_INVM      (OFF_USER_O + NUH)
#define OFF_GATEM     (OFF_INVM + NMc)
#define OFF_C1        (OFF_GATEM + NMc)
#define OFF_V1        (OFF_C1 + 128)
#define BUF_TOTAL     (OFF_V1 + 128)

__device__ float g_buf[BUF_TOTAL];
__device__ int   g_deg[NUc + NMc];

// int scratch: CSR structures
#define IOFF_CSRU   ((size_t)0)                 // E
#define IOFF_CSRM   (IOFF_CSRU + Ec)            // E
#define IOFF_STARTU (IOFF_CSRM + Ec)            // NU+1
#define IOFF_STARTM (IOFF_STARTU + NUc + 1)     // NM+1
#define IOFF_CURSU  (IOFF_STARTM + NMc + 1)     // NU
#define IOFF_CURSM  (IOFF_CURSU + NUc)          // NM
#define IOFF_INCL   (IOFF_CURSM + NMc)          // max(NU,NM)
#define IOFF_BSUM   (IOFF_INCL + NUc)           // 256
#define IBUF_TOTAL  (IOFF_BSUM + 256)

__device__ int g_ibuf[IBUF_TOTAL];

typedef unsigned long long ull;

// ---------------- f32x2 packed-FMA helpers (Blackwell sm_100+) ----------------
__device__ __forceinline__ ull pk2(float lo, float hi) {
    ull r;
    asm("mov.b64 %0, {%1, %2};" : "=l"(r) : "f"(lo), "f"(hi));
    return r;
}
__device__ __forceinline__ void upk2(float& lo, float& hi, ull v) {
    asm("mov.b64 {%0, %1}, %2;" : "=f"(lo), "=f"(hi) : "l"(v));
}
__device__ __forceinline__ void ffma2(ull& d, ull a, ull b) {
    asm("fma.rn.f32x2 %0, %1, %2, %0;" : "+l"(d) : "l"(a), "l"(b));
}

// ---------------- degree counting ----------------
__global__ void k_deg(const int* __restrict__ src, const int* __restrict__ dst, int E) {
    int e = blockIdx.x * blockDim.x + threadIdx.x;
    if (e < E) {
        atomicAdd(&g_deg[src[e]], 1);
        atomicAdd(&g_deg[NUc + dst[e]], 1);
    }
}

// ---------------- scan: phase 1 (per-block inclusive scan + block sums) ----------------
__global__ __launch_bounds__(1024) void k_scan1(const int* __restrict__ deg,
                                                int* __restrict__ incl,
                                                int* __restrict__ bsum, int N) {
    __shared__ int sm[1024];
    int t = threadIdx.x;
    int i = blockIdx.x * 1024 + t;
    int v = (i < N) ? deg[i] : 0;
    sm[t] = v;
    __syncthreads();
#pragma unroll
    for (int o = 1; o < 1024; o <<= 1) {
        int x = (t >= o) ? sm[t - o] : 0;
        __syncthreads();
        sm[t] += x;
        __syncthreads();
    }
    if (i < N) incl[i] = sm[t];
    if (t == 1023) bsum[blockIdx.x] = sm[1023];
}

// ---------------- scan: phase 2 (exclusive scan of block sums, 1 block) ----------------
__global__ void k_scan2(int* __restrict__ bsum, int nb) {
    __shared__ int sm[256];
    int t = threadIdx.x;
    int v = (t < nb) ? bsum[t] : 0;
    sm[t] = v;
    __syncthreads();
#pragma unroll
    for (int o = 1; o < 256; o <<= 1) {
        int x = (t >= o) ? sm[t - o] : 0;
        __syncthreads();
        sm[t] += x;
        __syncthreads();
    }
    if (t < nb) bsum[t] = sm[t] - v;   // exclusive
}

// ---------------- scan: phase 3 (final offsets + cursors + inv/gate tables) ----------------
__global__ void k_scan3(const int* __restrict__ deg, const int* __restrict__ incl,
                        const int* __restrict__ bsum,
                        int* __restrict__ start, int* __restrict__ curs,
                        float* __restrict__ inv, float* __restrict__ gate, int N) {
    int i = blockIdx.x * blockDim.x + threadIdx.x;
    if (i >= N) return;
    int d = deg[i];
    int s = incl[i] - d + bsum[i >> 10];
    start[i] = s;
    curs[i]  = s;
    if (i == N - 1) start[N] = s + d;
    if (inv)  inv[i]  = 1.0f / (float)max(d, 1);
    if (gate) gate[i] = d > 0 ? 1.0f : 0.0f;
}

// ---------------- edge scatter into both CSRs ----------------
__global__ void k_scatter(const int* __restrict__ src, const int* __restrict__ dst,
                          int* __restrict__ cursU, int* __restrict__ cursM,
                          int* __restrict__ csrU, int* __restrict__ csrM, int E) {
    int e = blockIdx.x * blockDim.x + threadIdx.x;
    if (e >= E) return;
    int u = src[e], m = dst[e];
    csrU[atomicAdd(cursU + u, 1)] = m;
    csrM[atomicAdd(cursM + m, 1)] = u;
}

// ---------------- collapsed user_init terms ----------------
__global__ void k_vec(const float* __restrict__ u0, const float* __restrict__ Wl1_um,
                      const float* __restrict__ Wr1_mu, const float* __restrict__ bl1_mu,
                      float* __restrict__ c1, float* __restrict__ v1) {
    int n = threadIdx.x;
    float c = 0.0f, v = 0.0f;
    for (int k = 0; k < Hc; k++) {
        float uk = u0[k];
        c += uk * Wl1_um[k * Hc + n];
        v += uk * Wr1_mu[k * Hc + n];
    }
    c1[n] = c;
    v1[n] = bl1_mu[n] + v;
}

// ---------------- pipelined SGEMM with f32x2 packed FMAs ----------------
// C[M,128] = epilogue(A[M,K] @ W[K,128])
// epilogue: t = ascale[row]*acc + bias[n] + gate[row]*gvec[n] + Cadd[row,n]
//           (null -> scale 1 / term 0); optional relu; output row stride ldc.
__global__ __launch_bounds__(256, 2) void k_gemm(
    const float* __restrict__ A, const float* __restrict__ W, float* __restrict__ C,
    int M, int K, int ldc,
    const float* __restrict__ bias,
    const float* __restrict__ ascale,
    const float* __restrict__ Cadd,
    const float* __restrict__ gate, const float* __restrict__ gvec,
    int do_relu)
{
    __shared__ float As[16][128];   // [k][m], m contiguous -> row pairs pack free
    __shared__ float Ws[16][128];   // [k][n], n contiguous

    int tid = threadIdx.x;
    int tx = tid & 15;         // output cols tx*8 .. tx*8+7
    int ty = tid >> 4;         // output rows ty*8 .. ty*8+7
    int brow = blockIdx.x * 128;

    // acc2[ip][j] holds packed rows (ty*8+2ip, ty*8+2ip+1) for col tx*8+j
    ull acc2[4][8];
#pragma unroll
    for (int i = 0; i < 4; i++)
#pragma unroll
        for (int j = 0; j < 8; j++) acc2[i][j] = 0ull;

    float4 a_st[2], w_st[2];

    auto load_tiles = [&](int k0) {
#pragma unroll
        for (int it = 0; it < 2; it++) {
            int s = it * 256 + tid;
            int m = s >> 2;
            int k4 = (s & 3) << 2;
            int row = brow + m;
            a_st[it] = (row < M)
                ? *reinterpret_cast<const float4*>(A + (size_t)row * K + k0 + k4)
                : make_float4(0.f, 0.f, 0.f, 0.f);
            int kw = s >> 5;
            int n4 = (s & 31) << 2;
            w_st[it] = *reinterpret_cast<const float4*>(W + (size_t)(k0 + kw) * Hc + n4);
        }
    };

    load_tiles(0);
    int nt = K >> 4;
    for (int t = 0; t < nt; t++) {
        // stage -> smem
#pragma unroll
        for (int it = 0; it < 2; it++) {
            int s = it * 256 + tid;
            int m = s >> 2;
            int k4 = (s & 3) << 2;
            As[k4 + 0][m] = a_st[it].x;
            As[k4 + 1][m] = a_st[it].y;
            As[k4 + 2][m] = a_st[it].z;
            As[k4 + 3][m] = a_st[it].w;
            int kw = s >> 5;
            int n4 = (s & 31) << 2;
            *reinterpret_cast<float4*>(&Ws[kw][n4]) = w_st[it];
        }
        __syncthreads();

        // prefetch next tile into registers (overlaps with FMAs below)
        if (t + 1 < nt) load_tiles((t + 1) << 4);

#pragma unroll
        for (int kk = 0; kk < 16; kk++) {
            // A row pairs come packed straight out of smem (m contiguous)
            ulonglong2 av0 = *reinterpret_cast<const ulonglong2*>(&As[kk][ty * 8]);
            ulonglong2 av1 = *reinterpret_cast<const ulonglong2*>(&As[kk][ty * 8 + 4]);
            ull ap[4] = {av0.x, av0.y, av1.x, av1.y};

            float4 b0 = *reinterpret_cast<const float4*>(&Ws[kk][tx * 8]);
            float4 b1 = *reinterpret_cast<const float4*>(&Ws[kk][tx * 8 + 4]);
            ull bd[8] = {pk2(b0.x, b0.x), pk2(b0.y, b0.y), pk2(b0.z, b0.z), pk2(b0.w, b0.w),
                         pk2(b1.x, b1.x), pk2(b1.y, b1.y), pk2(b1.z, b1.z), pk2(b1.w, b1.w)};

#pragma unroll
            for (int ip = 0; ip < 4; ip++)
#pragma unroll
                for (int j = 0; j < 8; j++)
                    ffma2(acc2[ip][j], ap[ip], bd[j]);
        }
        __syncthreads();
    }

    // unpack accumulators: acc[i][j], i = local row (0..7)
    float acc[8][8];
#pragma unroll
    for (int ip = 0; ip < 4; ip++)
#pragma unroll
        for (int j = 0; j < 8; j++)
            upk2(acc[2 * ip][j], acc[2 * ip + 1][j], acc2[ip][j]);

    // epilogue
#pragma unroll
    for (int i = 0; i < 8; i++) {
        int row = brow + ty * 8 + i;
        if (row >= M) continue;
        float as_ = ascale ? ascale[row] : 1.0f;
        float g_  = gate   ? gate[row]   : 0.0f;
#pragma unroll
        for (int jj = 0; jj < 2; jj++) {
            int nb = tx * 8 + jj * 4;
            float4 cadd = make_float4(0.f, 0.f, 0.f, 0.f);
            if (Cadd)
                cadd = *reinterpret_cast<const float4*>(Cadd + (size_t)row * Hc + nb);
            float ca[4] = {cadd.x, cadd.y, cadd.z, cadd.w};
            float4 v;
            float* vp = &v.x;
#pragma unroll
            for (int j = 0; j < 4; j++) {
                int n = nb + j;
                float tacc = acc[i][jj * 4 + j] * as_;
                if (bias) tacc += bias[n];
                if (gvec) tacc += g_ * gvec[n];
                if (Cadd) tacc += ca[j];
                if (do_relu) tacc = fmaxf(tacc, 0.0f);
                vp[j] = tacc;
            }
            *reinterpret_cast<float4*>(C + (size_t)row * ldc + nb) = v;
        }
    }
}

// ---------------- fused user aggregation over CSR (t1+t2 interleaved table) ----------------
// uh[u]     = relu( inv * sum_m t1[m] + v1 ),  inv = 1/max(deg,1)
// umean2[u] = inv * sum_m t2[m]
__global__ void k_agg_user(const float4* __restrict__ t1t2, const int* __restrict__ csr,
                           const int* __restrict__ start, const float* __restrict__ v1,
                           float4* __restrict__ uh, float4* __restrict__ umean2) {
    int u = blockIdx.x * (blockDim.x >> 5) + (threadIdx.x >> 5);
    if (u >= NUc) return;
    int lane = threadIdx.x & 31;
    int s = start[u], e = start[u + 1];

    float4 a1 = make_float4(0.f, 0.f, 0.f, 0.f);
    float4 a2 = make_float4(0.f, 0.f, 0.f, 0.f);
    int j = s;
    for (; j + 1 < e; j += 2) {
        int m0 = __ldg(csr + j);
        int m1 = __ldg(csr + j + 1);
        const float4* r0 = t1t2 + (size_t)m0 * 64;
        const float4* r1 = t1t2 + (size_t)m1 * 64;
        float4 x0 = __ldg(r0 + lane);
        float4 y0 = __ldg(r0 + 32 + lane);
        float4 x1 = __ldg(r1 + lane);
        float4 y1 = __ldg(r1 + 32 + lane);
        a1.x += x0.x + x1.x; a1.y += x0.y + x1.y; a1.z += x0.z + x1.z; a1.w += x0.w + x1.w;
        a2.x += y0.x + y1.x; a2.y += y0.y + y1.y; a2.z += y0.z + y1.z; a2.w += y0.w + y1.w;
    }
    if (j < e) {
        int m0 = __ldg(csr + j);
        const float4* r0 = t1t2 + (size_t)m0 * 64;
        float4 x0 = __ldg(r0 + lane);
        float4 y0 = __ldg(r0 + 32 + lane);
        a1.x += x0.x; a1.y += x0.y; a1.z += x0.z; a1.w += x0.w;
        a2.x += y0.x; a2.y += y0.y; a2.z += y0.z; a2.w += y0.w;
    }

    float inv = 1.0f / (float)max(e - s, 1);
    float4 vv = reinterpret_cast<const float4*>(v1)[lane];
    float4 r;
    r.x = fmaxf(a1.x * inv + vv.x, 0.0f);
    r.y = fmaxf(a1.y * inv + vv.y, 0.0f);
    r.z = fmaxf(a1.z * inv + vv.z, 0.0f);
    r.w = fmaxf(a1.w * inv + vv.w, 0.0f);
    float4 m2;
    m2.x = a2.x * inv; m2.y = a2.y * inv; m2.z = a2.z * inv; m2.w = a2.w * inv;
    size_t o = (size_t)u * 32 + lane;
    uh[o] = r;
    umean2[o] = m2;
}

// ---------------- movie aggregation over CSR: msum[m] = sum_u user_h[u] ----------------
__global__ void k_agg_movie(const float4* __restrict__ uh, const int* __restrict__ csr,
                            const int* __restrict__ start, float4* __restrict__ msum) {
    int m = blockIdx.x * (blockDim.x >> 5) + (threadIdx.x >> 5);
    if (m >= NMc) return;
    int lane = threadIdx.x & 31;
    int s = start[m], e = start[m + 1];

    float4 a = make_float4(0.f, 0.f, 0.f, 0.f);
    int j = s;
    for (; j + 1 < e; j += 2) {
        int u0 = __ldg(csr + j);
        int u1 = __ldg(csr + j + 1);
        float4 x0 = __ldg(uh + (size_t)u0 * 32 + lane);
        float4 x1 = __ldg(uh + (size_t)u1 * 32 + lane);
        a.x += x0.x + x1.x; a.y += x0.y + x1.y; a.z += x0.z + x1.z; a.w += x0.w + x1.w;
    }
    if (j < e) {
        float4 x0 = __ldg(uh + (size_t)__ldg(csr + j) * 32 + lane);
        a.x += x0.x; a.y += x0.y; a.z += x0.z; a.w += x0.w;
    }
    msum[(size_t)m * 32 + lane] = a;
}

// ---------------- supervision-edge dot products ----------------
__global__ void k_dot(const float4* __restrict__ uo, const float4* __restrict__ mo,
                      const int* __restrict__ lu, const int* __restrict__ lm,
                      float* __restrict__ out, int EL) {
    int e = (blockIdx.x * blockDim.x + threadIdx.x) >> 5;
    if (e >= EL) return;
    int lane = threadIdx.x & 31;
    float4 a = __ldg(uo + (size_t)__ldg(lu + e) * 32 + lane);
    float4 b = __ldg(mo + (size_t)__ldg(lm + e) * 32 + lane);
    float s = a.x * b.x + a.y * b.y + a.z * b.z + a.w * b.w;
#pragma unroll
    for (int o = 16; o; o >>= 1) s += __shfl_xor_sync(0xffffffffu, s, o);
    if (lane == 0) out[e] = s;
}

// ---------------- launcher ----------------
extern "C" void kernel_launch(void* const* d_in, const int* in_sizes, int n_in,
                              void* d_out, int out_size) {
    int wb = n_in - 14;  // weights are the last 14 inputs

    const float* movie_feats = (const float*)d_in[0];
    const float* user_init   = (const float*)d_in[1];
    const int*   edge_src    = (const int*)d_in[2];
    const int*   edge_dst    = (const int*)d_in[3];
    const int*   lbl_user    = (const int*)d_in[4];
    const int*   lbl_movie   = (const int*)d_in[5];

    const float* Wm     = (const float*)d_in[wb + 0];
    const float* bm     = (const float*)d_in[wb + 1];
    const float* Wl1_um = (const float*)d_in[wb + 2];
    const float* bl1_um = (const float*)d_in[wb + 3];
    const float* Wr1_um = (const float*)d_in[wb + 4];
    const float* Wl1_mu = (const float*)d_in[wb + 5];
    const float* bl1_mu = (const float*)d_in[wb + 6];
    const float* Wr1_mu = (const float*)d_in[wb + 7];
    const float* Wl2_um = (const float*)d_in[wb + 8];
    const float* bl2_um = (const float*)d_in[wb + 9];
    const float* Wr2_um = (const float*)d_in[wb + 10];
    const float* Wl2_mu = (const float*)d_in[wb + 11];
    const float* bl2_mu = (const float*)d_in[wb + 12];
    const float* Wr2_mu = (const float*)d_in[wb + 13];

    float* out = (float*)d_out;

    float* buf = nullptr;
    int*   deg = nullptr;
    int*   ibuf = nullptr;
    cudaGetSymbolAddress((void**)&buf, g_buf);
    cudaGetSymbolAddress((void**)&deg, g_deg);
    cudaGetSymbolAddress((void**)&ibuf, g_ibuf);

    float* movie_x   = buf + OFF_MOVIE_X;
    float* t1t2      = buf + OFF_T1T2;
    float* movie_h   = buf + OFF_MOVIE_H;
    float* movie_tmp = buf + OFF_MOVIE_TMP;
    float* msum      = buf + OFF_MSUM;
    float* movie_o   = buf + OFF_MOVIE_O;
    float* user_h    = buf + OFF_USER_H;
    float* umean2    = buf + OFF_UMEAN2;
    float* user_o    = buf + OFF_USER_O;
    float* invM      = buf + OFF_INVM;
    float* gateM     = buf + OFF_GATEM;
    float* c1        = buf + OFF_C1;
    float* v1        = buf + OFF_V1;

    int* csrU   = ibuf + IOFF_CSRU;
    int* csrM   = ibuf + IOFF_CSRM;
    int* startU = ibuf + IOFF_STARTU;
    int* startM = ibuf + IOFF_STARTM;
    int* cursU  = ibuf + IOFF_CURSU;
    int* cursM  = ibuf + IOFF_CURSM;
    int* incl   = ibuf + IOFF_INCL;
    int* bsum   = ibuf + IOFF_BSUM;

    const int nbU = (NUc + 1023) / 1024;   // 196
    const int nbM = (NMc + 1023) / 1024;   // 79
    const int gemmM_blocks = NMc / 128;                 // 625
    const int gemmU_blocks = (NUc + 127) / 128;         // 1563

    // -------- CSR build --------
    cudaMemsetAsync(deg, 0, sizeof(int) * (NUc + NMc));
    k_deg<<<(Ec + 255) / 256, 256>>>(edge_src, edge_dst, Ec);

    k_scan1<<<nbU, 1024>>>(deg, incl, bsum, NUc);
    k_scan2<<<1, 256>>>(bsum, nbU);
    k_scan3<<<nbU, 1024>>>(deg, incl, bsum, startU, cursU, nullptr, nullptr, NUc);

    k_scan1<<<nbM, 1024>>>(deg + NUc, incl, bsum, NMc);
    k_scan2<<<1, 256>>>(bsum, nbM);
    k_scan3<<<nbM, 1024>>>(deg + NUc, incl, bsum, startM, cursM, invM, gateM, NMc);

    k_scatter<<<(Ec + 255) / 256, 256>>>(edge_src, edge_dst, cursU, cursM, csrU, csrM, Ec);

    // collapsed user_init terms
    k_vec<<<1, 128>>>(user_init, Wl1_um, Wr1_mu, bl1_mu, c1, v1);

    // -------- GEMM chain (movie side) --------
    k_gemm<<<gemmM_blocks, 256>>>(movie_feats, Wm, movie_x, NMc, FDc, Hc,
                                  bm, nullptr, nullptr, nullptr, nullptr, 0);
    k_gemm<<<gemmM_blocks, 256>>>(movie_x, Wl1_mu, t1t2, NMc, Hc, 256,
                                  nullptr, nullptr, nullptr, nullptr, nullptr, 0);
    k_gemm<<<gemmM_blocks, 256>>>(movie_x, Wr1_um, movie_h, NMc, Hc, Hc,
                                  bl1_um, nullptr, nullptr, gateM, c1, 1);
    k_gemm<<<gemmM_blocks, 256>>>(movie_h, Wl2_mu, t1t2 + 128, NMc, Hc, 256,
                                  nullptr, nullptr, nullptr, nullptr, nullptr, 0);
    k_gemm<<<gemmM_blocks, 256>>>(movie_h, Wr2_um, movie_tmp, NMc, Hc, Hc,
                                  nullptr, nullptr, nullptr, nullptr, nullptr, 0);

    // -------- aggregations (CSR gather, no atomics, no memsets) --------
    k_agg_user<<<(NUc + 7) / 8, 256>>>((const float4*)t1t2, csrU, startU, v1,
                                       (float4*)user_h, (float4*)umean2);
    k_agg_movie<<<(NMc + 7) / 8, 256>>>((const float4*)user_h, csrM, startM,
                                        (float4*)msum);

    // -------- output GEMMs --------
    // movie_o = invM*(msum @ Wl2_um) + bl2_um + movie_tmp
    k_gemm<<<gemmM_blocks, 256>>>(msum, Wl2_um, movie_o, NMc, Hc, Hc,
                                  bl2_um, invM, movie_tmp, nullptr, nullptr, 0);
    // user_o = user_h @ Wr2_mu + bl2_mu + umean2
    k_gemm<<<gemmU_blocks, 256>>>(user_h, Wr2_mu, user_o, NUc, Hc, Hc,
                                  bl2_mu, nullptr, umean2, nullptr, nullptr, 0);

    // out[e] = dot(user_o[lbl_user[e]], movie_o[lbl_movie[e]])
    k_dot<<<(ELc + 7) / 8, 256>>>((const float4*)user_o, (const float4*)movie_o,
                                  lbl_user, lbl_movie, out, ELc);
}

// round 7
// speedup vs baseline: 1.6786x; 1.1133x over previous
#include <cuda_runtime.h>
#include <cstdint>
#include <cstddef>

// ---------------- problem constants (fixed-shape problem) ----------------
#define Hc   128
#define NUc  200000
#define NMc  80000
#define Ec   2000000
#define ELc  500000
#define FDc  512

#define NMH  (NMc * Hc)            // 10,240,000 floats
#define NUH  ((size_t)NUc * Hc)    // 25,600,000 floats

// ---------------- static scratch (no allocations allowed) ----------------
#define OFF_MOVIE_X   ((size_t)0)
#define OFF_T1T2      (OFF_MOVIE_X + NMH)            // interleaved [NM][256]: t1 | t2
#define OFF_MOVIE_H   (OFF_T1T2 + (size_t)2 * NMH)
#define OFF_MOVIE_TMP (OFF_MOVIE_H + NMH)
#define OFF_MSUM      (OFF_MOVIE_TMP + NMH)
#define OFF_MOVIE_O   (OFF_MSUM + NMH)
#define OFF_MOVIE_O2  (OFF_MOVIE_O + NMH)
#define OFF_USER_H    (OFF_MOVIE_O2 + NMH)
#define OFF_UB        (OFF_USER_H + NUH)             // umean2 + bl2_mu
#define OFF_INVM      (OFF_UB + NUH)
#define OFF_GATEM     (OFF_INVM + NMc)
#define OFF_C1        (OFF_GATEM + NMc)
#define OFF_V1        (OFF_C1 + 128)
#define OFF_WT        (OFF_V1 + 128)                 // Wr2_mu^T, 128*128
#define BUF_TOTAL     (OFF_WT + Hc * Hc)

__device__ float g_buf[BUF_TOTAL];
__device__ int   g_deg[NUc + NMc];

// int scratch: CSR structures
#define IOFF_CSRU   ((size_t)0)                 // E
#define IOFF_CSRM   (IOFF_CSRU + Ec)            // E
#define IOFF_STARTU (IOFF_CSRM + Ec)            // NU+1
#define IOFF_STARTM (IOFF_STARTU + NUc + 1)     // NM+1
#define IOFF_CURSU  (IOFF_STARTM + NMc + 1)     // NU
#define IOFF_CURSM  (IOFF_CURSU + NUc)          // NM
#define IOFF_INCL   (IOFF_CURSM + NMc)          // max(NU,NM)
#define IOFF_BSUM   (IOFF_INCL + NUc)           // 256
#define IBUF_TOTAL  (IOFF_BSUM + 256)

__device__ int g_ibuf[IBUF_TOTAL];

typedef unsigned long long ull;

// ---------------- f32x2 packed-FMA helpers (Blackwell sm_100+) ----------------
__device__ __forceinline__ ull pk2(float lo, float hi) {
    ull r;
    asm("mov.b64 %0, {%1, %2};" : "=l"(r) : "f"(lo), "f"(hi));
    return r;
}
__device__ __forceinline__ void upk2(float& lo, float& hi, ull v) {
    asm("mov.b64 {%0, %1}, %2;" : "=f"(lo), "=f"(hi) : "l"(v));
}
__device__ __forceinline__ void ffma2(ull& d, ull a, ull b) {
    asm("fma.rn.f32x2 %0, %1, %2, %0;" : "+l"(d) : "l"(a), "l"(b));
}

// ---------------- degree counting ----------------
__global__ void k_deg(const int* __restrict__ src, const int* __restrict__ dst, int E) {
    int e = blockIdx.x * blockDim.x + threadIdx.x;
    if (e < E) {
        atomicAdd(&g_deg[src[e]], 1);
        atomicAdd(&g_deg[NUc + dst[e]], 1);
    }
}

// ---------------- scan: phase 1 ----------------
__global__ __launch_bounds__(1024) void k_scan1(const int* __restrict__ deg,
                                                int* __restrict__ incl,
                                                int* __restrict__ bsum, int N) {
    __shared__ int sm[1024];
    int t = threadIdx.x;
    int i = blockIdx.x * 1024 + t;
    int v = (i < N) ? deg[i] : 0;
    sm[t] = v;
    __syncthreads();
#pragma unroll
    for (int o = 1; o < 1024; o <<= 1) {
        int x = (t >= o) ? sm[t - o] : 0;
        __syncthreads();
        sm[t] += x;
        __syncthreads();
    }
    if (i < N) incl[i] = sm[t];
    if (t == 1023) bsum[blockIdx.x] = sm[1023];
}

// ---------------- scan: phase 2 ----------------
__global__ void k_scan2(int* __restrict__ bsum, int nb) {
    __shared__ int sm[256];
    int t = threadIdx.x;
    int v = (t < nb) ? bsum[t] : 0;
    sm[t] = v;
    __syncthreads();
#pragma unroll
    for (int o = 1; o < 256; o <<= 1) {
        int x = (t >= o) ? sm[t - o] : 0;
        __syncthreads();
        sm[t] += x;
        __syncthreads();
    }
    if (t < nb) bsum[t] = sm[t] - v;   // exclusive
}

// ---------------- scan: phase 3 ----------------
__global__ void k_scan3(const int* __restrict__ deg, const int* __restrict__ incl,
                        const int* __restrict__ bsum,
                        int* __restrict__ start, int* __restrict__ curs,
                        float* __restrict__ inv, float* __restrict__ gate, int N) {
    int i = blockIdx.x * blockDim.x + threadIdx.x;
    if (i >= N) return;
    int d = deg[i];
    int s = incl[i] - d + bsum[i >> 10];
    start[i] = s;
    curs[i]  = s;
    if (i == N - 1) start[N] = s + d;
    if (inv)  inv[i]  = 1.0f / (float)max(d, 1);
    if (gate) gate[i] = d > 0 ? 1.0f : 0.0f;
}

// ---------------- edge scatter into both CSRs ----------------
__global__ void k_scatter(const int* __restrict__ src, const int* __restrict__ dst,
                          int* __restrict__ cursU, int* __restrict__ cursM,
                          int* __restrict__ csrU, int* __restrict__ csrM, int E) {
    int e = blockIdx.x * blockDim.x + threadIdx.x;
    if (e >= E) return;
    int u = src[e], m = dst[e];
    csrU[atomicAdd(cursU + u, 1)] = m;
    csrM[atomicAdd(cursM + m, 1)] = u;
}

// ---------------- collapsed user_init terms ----------------
__global__ void k_vec(const float* __restrict__ u0, const float* __restrict__ Wl1_um,
                      const float* __restrict__ Wr1_mu, const float* __restrict__ bl1_mu,
                      float* __restrict__ c1, float* __restrict__ v1) {
    int n = threadIdx.x;
    float c = 0.0f, v = 0.0f;
    for (int k = 0; k < Hc; k++) {
        float uk = u0[k];
        c += uk * Wl1_um[k * Hc + n];
        v += uk * Wr1_mu[k * Hc + n];
    }
    c1[n] = c;
    v1[n] = bl1_mu[n] + v;
}

// ---------------- 128x128 transpose (for Wr2_mu^T) ----------------
__global__ void k_transp(const float* __restrict__ in, float* __restrict__ outw) {
    __shared__ float tile[32][33];
    int bx = blockIdx.x & 3, by = blockIdx.x >> 2;
    int x = bx * 32 + threadIdx.x, y = by * 32 + threadIdx.y;
    tile[threadIdx.y][threadIdx.x] = in[y * Hc + x];
    __syncthreads();
    outw[(bx * 32 + threadIdx.y) * Hc + by * 32 + threadIdx.x] = tile[threadIdx.x][threadIdx.y];
}

// ---------------- GEMM core: double-buffered smem, f32x2 FMAs ----------------
// C[M,128] = epilogue(A[M,K] @ W[K,128])
// epilogue: t = ascale[row]*acc + bias[n] + gate[row]*gvec[n] + Cadd[row,n]
__device__ __forceinline__ void gemm_core(
    const float* __restrict__ A, const float* __restrict__ W, float* __restrict__ C,
    int M, int K, int ldc,
    const float* __restrict__ bias,
    const float* __restrict__ ascale,
    const float* __restrict__ Cadd,
    const float* __restrict__ gate, const float* __restrict__ gvec,
    int do_relu)
{
    __shared__ float As[2][16][128];   // [buf][k][m]
    __shared__ float Ws[2][16][128];   // [buf][k][n]

    int tid = threadIdx.x;
    int tx = tid & 15;         // output cols tx*8 .. tx*8+7
    int ty = tid >> 4;         // output rows ty*8 .. ty*8+7
    int brow = blockIdx.x * 128;

    ull acc2[4][8];
#pragma unroll
    for (int i = 0; i < 4; i++)
#pragma unroll
        for (int j = 0; j < 8; j++) acc2[i][j] = 0ull;

    float4 a_st[2], w_st[2];

    auto ldg_tiles = [&](int k0) {
#pragma unroll
        for (int it = 0; it < 2; it++) {
            int s = it * 256 + tid;
            int m = s >> 2;
            int k4 = (s & 3) << 2;
            int row = brow + m;
            a_st[it] = (row < M)
                ? *reinterpret_cast<const float4*>(A + (size_t)row * K + k0 + k4)
                : make_float4(0.f, 0.f, 0.f, 0.f);
            int kw = s >> 5;
            int n4 = (s & 31) << 2;
            w_st[it] = *reinterpret_cast<const float4*>(W + (size_t)(k0 + kw) * Hc + n4);
        }
    };
    auto sts_tiles = [&](int b) {
#pragma unroll
        for (int it = 0; it < 2; it++) {
            int s = it * 256 + tid;
            int m = s >> 2;
            int k4 = (s & 3) << 2;
            As[b][k4 + 0][m] = a_st[it].x;
            As[b][k4 + 1][m] = a_st[it].y;
            As[b][k4 + 2][m] = a_st[it].z;
            As[b][k4 + 3][m] = a_st[it].w;
            int kw = s >> 5;
            int n4 = (s & 31) << 2;
            *reinterpret_cast<float4*>(&Ws[b][kw][n4]) = w_st[it];
        }
    };

    ldg_tiles(0);
    sts_tiles(0);
    __syncthreads();

    int nt = K >> 4;
    for (int t = 0; t < nt; t++) {
        int cur = t & 1;
        if (t + 1 < nt) ldg_tiles((t + 1) << 4);

#pragma unroll
        for (int kk = 0; kk < 16; kk++) {
            ulonglong2 av0 = *reinterpret_cast<const ulonglong2*>(&As[cur][kk][ty * 8]);
            ulonglong2 av1 = *reinterpret_cast<const ulonglong2*>(&As[cur][kk][ty * 8 + 4]);
            ull ap[4] = {av0.x, av0.y, av1.x, av1.y};

            float4 b0 = *reinterpret_cast<const float4*>(&Ws[cur][kk][tx * 8]);
            float4 b1 = *reinterpret_cast<const float4*>(&Ws[cur][kk][tx * 8 + 4]);
            ull bd[8] = {pk2(b0.x, b0.x), pk2(b0.y, b0.y), pk2(b0.z, b0.z), pk2(b0.w, b0.w),
                         pk2(b1.x, b1.x), pk2(b1.y, b1.y), pk2(b1.z, b1.z), pk2(b1.w, b1.w)};

#pragma unroll
            for (int ip = 0; ip < 4; ip++)
#pragma unroll
                for (int j = 0; j < 8; j++)
                    ffma2(acc2[ip][j], ap[ip], bd[j]);
        }

        if (t + 1 < nt) sts_tiles(cur ^ 1);
        __syncthreads();
    }

    float acc[8][8];
#pragma unroll
    for (int ip = 0; ip < 4; ip++)
#pragma unroll
        for (int j = 0; j < 8; j++)
            upk2(acc[2 * ip][j], acc[2 * ip + 1][j], acc2[ip][j]);

    // epilogue
#pragma unroll
    for (int i = 0; i < 8; i++) {
        int row = brow + ty * 8 + i;
        if (row >= M) continue;
        float as_ = ascale ? ascale[row] : 1.0f;
        float g_  = gate   ? gate[row]   : 0.0f;
#pragma unroll
        for (int jj = 0; jj < 2; jj++) {
            int nb = tx * 8 + jj * 4;
            float4 cadd = make_float4(0.f, 0.f, 0.f, 0.f);
            if (Cadd)
                cadd = *reinterpret_cast<const float4*>(Cadd + (size_t)row * Hc + nb);
            float ca[4] = {cadd.x, cadd.y, cadd.z, cadd.w};
            float4 v;
            float* vp = &v.x;
#pragma unroll
            for (int j = 0; j < 4; j++) {
                int n = nb + j;
                float tacc = acc[i][jj * 4 + j] * as_;
                if (bias) tacc += bias[n];
                if (gvec) tacc += g_ * gvec[n];
                if (Cadd) tacc += ca[j];
                if (do_relu) tacc = fmaxf(tacc, 0.0f);
                vp[j] = tacc;
            }
            *reinterpret_cast<float4*>(C + (size_t)row * ldc + nb) = v;
        }
    }
}

__global__ __launch_bounds__(256, 2) void k_gemm(
    const float* __restrict__ A, const float* __restrict__ W, float* __restrict__ C,
    int M, int K, int ldc,
    const float* __restrict__ bias, const float* __restrict__ ascale,
    const float* __restrict__ Cadd,
    const float* __restrict__ gate, const float* __restrict__ gvec, int do_relu)
{
    gemm_core(A, W, C, M, K, ldc, bias, ascale, Cadd, gate, gvec, do_relu);
}

// two GEMMs sharing the same A, selected by blockIdx.y (merged launch -> one tail wave)
__global__ __launch_bounds__(256, 2) void k_gemm_dual(
    const float* __restrict__ A, int M, int K,
    const float* __restrict__ W0, float* __restrict__ C0, int ldc0,
    const float* __restrict__ bias0, const float* __restrict__ gate0,
    const float* __restrict__ gvec0, int relu0,
    const float* __restrict__ W1, float* __restrict__ C1, int ldc1,
    const float* __restrict__ bias1, const float* __restrict__ gate1,
    const float* __restrict__ gvec1, int relu1)
{
    bool sec = (blockIdx.y != 0);
    gemm_core(A,
              sec ? W1 : W0, sec ? C1 : C0, M, K, sec ? ldc1 : ldc0,
              sec ? bias1 : bias0, nullptr, nullptr,
              sec ? gate1 : gate0, sec ? gvec1 : gvec0,
              sec ? relu1 : relu0);
}

// ---------------- fused user aggregation over CSR (t1+t2 interleaved table) ----------------
// uh[u] = relu( inv * sum_m t1[m] + v1 ),  inv = 1/max(deg,1)
// ub[u] = inv * sum_m t2[m] + bl2_mu       (the "rest" of user_o besides user_h@Wr2_mu)
__global__ void k_agg_user(const float4* __restrict__ t1t2, const int* __restrict__ csr,
                           const int* __restrict__ start, const float* __restrict__ v1,
                           const float* __restrict__ bl2,
                           float4* __restrict__ uh, float4* __restrict__ ub) {
    int u = blockIdx.x * (blockDim.x >> 5) + (threadIdx.x >> 5);
    if (u >= NUc) return;
    int lane = threadIdx.x & 31;
    int s = start[u], e = start[u + 1];

    float4 a1 = make_float4(0.f, 0.f, 0.f, 0.f);
    float4 a2 = make_float4(0.f, 0.f, 0.f, 0.f);
    int j = s;
    for (; j + 1 < e; j += 2) {
        int m0 = __ldg(csr + j);
        int m1 = __ldg(csr + j + 1);
        const float4* r0 = t1t2 + (size_t)m0 * 64;
        const float4* r1 = t1t2 + (size_t)m1 * 64;
        float4 x0 = __ldg(r0 + lane);
        float4 y0 = __ldg(r0 + 32 + lane);
        float4 x1 = __ldg(r1 + lane);
        float4 y1 = __ldg(r1 + 32 + lane);
        a1.x += x0.x + x1.x; a1.y += x0.y + x1.y; a1.z += x0.z + x1.z; a1.w += x0.w + x1.w;
        a2.x += y0.x + y1.x; a2.y += y0.y + y1.y; a2.z += y0.z + y1.z; a2.w += y0.w + y1.w;
    }
    if (j < e) {
        int m0 = __ldg(csr + j);
        const float4* r0 = t1t2 + (size_t)m0 * 64;
        float4 x0 = __ldg(r0 + lane);
        float4 y0 = __ldg(r0 + 32 + lane);
        a1.x += x0.x; a1.y += x0.y; a1.z += x0.z; a1.w += x0.w;
        a2.x += y0.x; a2.y += y0.y; a2.z += y0.z; a2.w += y0.w;
    }

    float inv = 1.0f / (float)max(e - s, 1);
    float4 vv = reinterpret_cast<const float4*>(v1)[lane];
    float4 bb = reinterpret_cast<const float4*>(bl2)[lane];
    float4 r;
    r.x = fmaxf(a1.x * inv + vv.x, 0.0f);
    r.y = fmaxf(a1.y * inv + vv.y, 0.0f);
    r.z = fmaxf(a1.z * inv + vv.z, 0.0f);
    r.w = fmaxf(a1.w * inv + vv.w, 0.0f);
    float4 m2;
    m2.x = a2.x * inv + bb.x;
    m2.y = a2.y * inv + bb.y;
    m2.z = a2.z * inv + bb.z;
    m2.w = a2.w * inv + bb.w;
    size_t o = (size_t)u * 32 + lane;
    uh[o] = r;
    ub[o] = m2;
}

// ---------------- movie aggregation over CSR: msum[m] = sum_u user_h[u] ----------------
__global__ void k_agg_movie(const float4* __restrict__ uh, const int* __restrict__ csr,
                            const int* __restrict__ start, float4* __restrict__ msum) {
    int m = blockIdx.x * (blockDim.x >> 5) + (threadIdx.x >> 5);
    if (m >= NMc) return;
    int lane = threadIdx.x & 31;
    int s = start[m], e = start[m + 1];

    float4 a = make_float4(0.f, 0.f, 0.f, 0.f);
    int j = s;
    for (; j + 1 < e; j += 2) {
        int u0 = __ldg(csr + j);
        int u1 = __ldg(csr + j + 1);
        float4 x0 = __ldg(uh + (size_t)u0 * 32 + lane);
        float4 x1 = __ldg(uh + (size_t)u1 * 32 + lane);
        a.x += x0.x + x1.x; a.y += x0.y + x1.y; a.z += x0.z + x1.z; a.w += x0.w + x1.w;
    }
    if (j < e) {
        float4 x0 = __ldg(uh + (size_t)__ldg(csr + j) * 32 + lane);
        a.x += x0.x; a.y += x0.y; a.z += x0.z; a.w += x0.w;
    }
    msum[(size_t)m * 32 + lane] = a;
}

// ---------------- supervision-edge dot products (two-term) ----------------
// out[e] = uh[u]·mo2[m] + ub[u]·mo[m]
__global__ void k_dot2(const float4* __restrict__ uh, const float4* __restrict__ ub,
                       const float4* __restrict__ mo, const float4* __restrict__ mo2,
                       const int* __restrict__ lu, const int* __restrict__ lm,
                       float* __restrict__ out, int EL) {
    int e = (blockIdx.x * blockDim.x + threadIdx.x) >> 5;
    if (e >= EL) return;
    int lane = threadIdx.x & 31;
    size_t ou = (size_t)__ldg(lu + e) * 32 + lane;
    size_t om = (size_t)__ldg(lm + e) * 32 + lane;
    float4 a  = __ldg(uh + ou);
    float4 a2 = __ldg(ub + ou);
    float4 b2 = __ldg(mo2 + om);
    float4 b  = __ldg(mo + om);
    float s = a.x * b2.x + a.y * b2.y + a.z * b2.z + a.w * b2.w
            + a2.x * b.x + a2.y * b.y + a2.z * b.z + a2.w * b.w;
#pragma unroll
    for (int o = 16; o; o >>= 1) s += __shfl_xor_sync(0xffffffffu, s, o);
    if (lane == 0) out[e] = s;
}

// ---------------- launcher ----------------
extern "C" void kernel_launch(void* const* d_in, const int* in_sizes, int n_in,
                              void* d_out, int out_size) {
    int wb = n_in - 14;  // weights are the last 14 inputs

    const float* movie_feats = (const float*)d_in[0];
    const float* user_init   = (const float*)d_in[1];
    const int*   edge_src    = (const int*)d_in[2];
    const int*   edge_dst    = (const int*)d_in[3];
    const int*   lbl_user    = (const int*)d_in[4];
    const int*   lbl_movie   = (const int*)d_in[5];

    const float* Wm     = (const float*)d_in[wb + 0];
    const float* bm     = (const float*)d_in[wb + 1];
    const float* Wl1_um = (const float*)d_in[wb + 2];
    const float* bl1_um = (const float*)d_in[wb + 3];
    const float* Wr1_um = (const float*)d_in[wb + 4];
    const float* Wl1_mu = (const float*)d_in[wb + 5];
    const float* bl1_mu = (const float*)d_in[wb + 6];
    const float* Wr1_mu = (const float*)d_in[wb + 7];
    const float* Wl2_um = (const float*)d_in[wb + 8];
    const float* bl2_um = (const float*)d_in[wb + 9];
    const float* Wr2_um = (const float*)d_in[wb + 10];
    const float* Wl2_mu = (const float*)d_in[wb + 11];
    const float* bl2_mu = (const float*)d_in[wb + 12];
    const float* Wr2_mu = (const float*)d_in[wb + 13];

    float* out = (float*)d_out;

    float* buf = nullptr;
    int*   deg = nullptr;
    int*   ibuf = nullptr;
    cudaGetSymbolAddress((void**)&buf, g_buf);
    cudaGetSymbolAddress((void**)&deg, g_deg);
    cudaGetSymbolAddress((void**)&ibuf, g_ibuf);

    float* movie_x   = buf + OFF_MOVIE_X;
    float* t1t2      = buf + OFF_T1T2;
    float* movie_h   = buf + OFF_MOVIE_H;
    float* movie_tmp = buf + OFF_MOVIE_TMP;
    float* msum      = buf + OFF_MSUM;
    float* movie_o   = buf + OFF_MOVIE_O;
    float* movie_o2  = buf + OFF_MOVIE_O2;
    float* user_h    = buf + OFF_USER_H;
    float* ub        = buf + OFF_UB;
    float* invM      = buf + OFF_INVM;
    float* gateM     = buf + OFF_GATEM;
    float* c1        = buf + OFF_C1;
    float* v1        = buf + OFF_V1;
    float* WT        = buf + OFF_WT;

    int* csrU   = ibuf + IOFF_CSRU;
    int* csrM   = ibuf + IOFF_CSRM;
    int* startU = ibuf + IOFF_STARTU;
    int* startM = ibuf + IOFF_STARTM;
    int* cursU  = ibuf + IOFF_CURSU;
    int* cursM  = ibuf + IOFF_CURSM;
    int* incl   = ibuf + IOFF_INCL;
    int* bsum   = ibuf + IOFF_BSUM;

    const int nbU = (NUc + 1023) / 1024;   // 196
    const int nbM = (NMc + 1023) / 1024;   // 79
    const int gemmM_blocks = NMc / 128;    // 625

    // -------- CSR build --------
    cudaMemsetAsync(deg, 0, sizeof(int) * (NUc + NMc));
    k_deg<<<(Ec + 255) / 256, 256>>>(edge_src, edge_dst, Ec);

    k_scan1<<<nbU, 1024>>>(deg, incl, bsum, NUc);
    k_scan2<<<1, 256>>>(bsum, nbU);
    k_scan3<<<nbU, 1024>>>(deg, incl, bsum, startU, cursU, nullptr, nullptr, NUc);

    k_scan1<<<nbM, 1024>>>(deg + NUc, incl, bsum, NMc);
    k_scan2<<<1, 256>>>(bsum, nbM);
    k_scan3<<<nbM, 1024>>>(deg + NUc, incl, bsum, startM, cursM, invM, gateM, NMc);

    k_scatter<<<(Ec + 255) / 256, 256>>>(edge_src, edge_dst, cursU, cursM, csrU, csrM, Ec);

    // collapsed user_init terms + transposed Wr2_mu
    k_vec<<<1, 128>>>(user_init, Wl1_um, Wr1_mu, bl1_mu, c1, v1);
    k_transp<<<16, dim3(32, 32)>>>(Wr2_mu, WT);

    // -------- GEMM chain (movie side) --------
    // movie_x = movie_feats @ Wm + bm   (K=512)
    k_gemm<<<gemmM_blocks, 256>>>(movie_feats, Wm, movie_x, NMc, FDc, Hc,
                                  bm, nullptr, nullptr, nullptr, nullptr, 0);
    // dual: t1 = movie_x@Wl1_mu (ldc=256) ; movie_h = relu(movie_x@Wr1_um + bl1_um + gateM*c1)
    k_gemm_dual<<<dim3(gemmM_blocks, 2), 256>>>(movie_x, NMc, Hc,
        Wl1_mu, t1t2, 256, nullptr, nullptr, nullptr, 0,
        Wr1_um, movie_h, Hc, bl1_um, gateM, c1, 1);
    // dual: t2 = movie_h@Wl2_mu (ldc=256, +128) ; movie_tmp = movie_h@Wr2_um
    k_gemm_dual<<<dim3(gemmM_blocks, 2), 256>>>(movie_h, NMc, Hc,
        Wl2_mu, t1t2 + 128, 256, nullptr, nullptr, nullptr, 0,
        Wr2_um, movie_tmp, Hc, nullptr, nullptr, nullptr, 0);

    // -------- aggregations (CSR gather, no atomics, no memsets) --------
    k_agg_user<<<(NUc + 7) / 8, 256>>>((const float4*)t1t2, csrU, startU, v1, bl2_mu,
                                       (float4*)user_h, (float4*)ub);
    k_agg_movie<<<(NMc + 7) / 8, 256>>>((const float4*)user_h, csrM, startM,
                                        (float4*)msum);

    // -------- output GEMMs --------
    // movie_o = invM*(msum @ Wl2_um) + bl2_um + movie_tmp
    k_gemm<<<gemmM_blocks, 256>>>(msum, Wl2_um, movie_o, NMc, Hc, Hc,
                                  bl2_um, invM, movie_tmp, nullptr, nullptr, 0);
    // movie_o2 = movie_o @ Wr2_mu^T
    k_gemm<<<gemmM_blocks, 256>>>(movie_o, WT, movie_o2, NMc, Hc, Hc,
                                  nullptr, nullptr, nullptr, nullptr, nullptr, 0);

    // out[e] = user_h[u]·movie_o2[m] + ub[u]·movie_o[m]
    k_dot2<<<(ELc + 7) / 8, 256>>>((const float4*)user_h, (const float4*)ub,
                                   (const float4*)movie_o, (const float4*)movie_o2,
                                   lbl_user, lbl_movie, out, ELc);
}